// round 2
// baseline (speedup 1.0000x reference)
#include <cuda_runtime.h>
#include <cstdint>

// ---------------- problem constants ----------------
#define B_     16
#define NPTS   4096
#define MIMG   1024
#define PD     256
#define ID     768
#define HD     512
#define OD     256
#define ROWS_IMG (B_*MIMG)   // 16384
#define ROWS_PT  (B_*NPTS)   // 65536

// ---------------- device scratch (no allocs allowed) ----------------
__device__ float g_W1ip[ID*HD];
__device__ float g_b1ip_f[HD];
__device__ float g_W1g_f[HD*HD];
__device__ float g_b1g_f[HD];
__device__ float g_W1d_f[HD*HD];
__device__ float g_b1d_f[HD];

__device__ float g_Hip[(size_t)ROWS_IMG*HD];        // 32 MB
__device__ float g_imgfeat[(size_t)ROWS_IMG*OD];    // 16 MB
__device__ float g_mean_img[ROWS_IMG];
__device__ float g_rstd_img[ROWS_IMG];

__device__ float g_fin[(size_t)ROWS_PT*(2*OD)];     // 128 MB
__device__ float g_mean_fin[ROWS_PT];
__device__ float g_rstd_fin[ROWS_PT];

__device__ float g_Hgd[(size_t)ROWS_PT*(2*HD)];     // 256 MB (gate hidden | delta hidden)
__device__ float g_GD[(size_t)ROWS_PT*(2*OD)];      // 128 MB (gate logits | delta)

// ---------------- helpers ----------------
__device__ __forceinline__ float warpSum(float v) {
#pragma unroll
    for (int o = 16; o > 0; o >>= 1) v += __shfl_xor_sync(0xffffffffu, v, o);
    return v;
}

__device__ __forceinline__ float gelu_exact(float x) {
    return 0.5f * x * (1.0f + erff(x * 0.7071067811865476f));
}

// ---------------- K0: fold LN affine into W1/b1 ----------------
__global__ void fold_w1_k(const float* __restrict__ lng, const float* __restrict__ w1,
                          float* __restrict__ out, int K, int N) {
    int i = blockIdx.x * blockDim.x + threadIdx.x;
    if (i < K * N) out[i] = lng[i / N] * w1[i];
}

__global__ void fold_b1_k(const float* __restrict__ lnb, const float* __restrict__ w1,
                          const float* __restrict__ b1, float* __restrict__ out, int K, int N) {
    int j = blockIdx.x * blockDim.x + threadIdx.x;
    if (j < N) {
        float s = b1[j];
        for (int k = 0; k < K; k++) s += lnb[k] * w1[(size_t)k * N + j];
        out[j] = s;
    }
}

// ---------------- K1: LN stats (mean, rstd) per row ----------------
__global__ void ln_stats_k(const float* __restrict__ X, int K,
                           float* __restrict__ mean, float* __restrict__ rstd) {
    int row = blockIdx.x;
    const float* x = X + (size_t)row * K;
    float s = 0.f, ss = 0.f;
    for (int k = threadIdx.x; k < K; k += blockDim.x) {
        float v = x[k];
        s += v; ss += v * v;
    }
    __shared__ float sbs[8], sbss[8];
    int lane = threadIdx.x & 31, wid = threadIdx.x >> 5;
    s = warpSum(s); ss = warpSum(ss);
    if (lane == 0) { sbs[wid] = s; sbss[wid] = ss; }
    __syncthreads();
    if (wid == 0) {
        s  = (lane < (blockDim.x >> 5)) ? sbs[lane]  : 0.f;
        ss = (lane < (blockDim.x >> 5)) ? sbss[lane] : 0.f;
        s = warpSum(s); ss = warpSum(ss);
        if (lane == 0) {
            float m = s / (float)K;
            float var = ss / (float)K - m * m;
            mean[row] = m;
            rstd[row] = rsqrtf(var + 1e-5f);
        }
    }
}

// ---------------- SGEMM: C[M,N] = act( A'[M,K] @ B[K,N] + bias ) ----------------
// A' = (A - mean[row]) * rstd[row] if LN_A.  Tiles: 128x128x16, 256 threads, 8x8 micro.
template<bool LN_A, bool DO_GELU>
__global__ __launch_bounds__(256) void sgemm_k(
    const float* __restrict__ A, int lda,
    const float* __restrict__ Bm, int ldb,
    const float* __restrict__ bias,
    float* __restrict__ C, int ldc,
    int Kdim,
    const float* __restrict__ mean, const float* __restrict__ rstd)
{
    __shared__ float As[16 * 132];   // padded, transposed: As[k*132 + m]
    __shared__ float Bs[16 * 128];   // Bs[k*128 + n]

    const int tid = threadIdx.x;
    const int tx = tid & 15;          // 0..15 -> 128 cols
    const int ty = tid >> 4;          // 0..15 -> 128 rows
    const int rowBase = blockIdx.y * 128;
    const int colBase = blockIdx.x * 128;

    const int aRow = tid >> 2;        // 0..63 (two passes, +64)
    const int aK   = (tid & 3) << 2;  // 0,4,8,12
    const int bRow = tid >> 5;        // 0..7 (two passes, +8)
    const int bCol = (tid & 31) << 2; // 0..124

    float m0 = 0.f, rs0 = 1.f, m1 = 0.f, rs1 = 1.f;
    if (LN_A) {
        m0 = mean[rowBase + aRow];        rs0 = rstd[rowBase + aRow];
        m1 = mean[rowBase + aRow + 64];   rs1 = rstd[rowBase + aRow + 64];
    }

    const float* Ab = A + (size_t)rowBase * lda;
    const float* Bb = Bm + colBase;

    float acc[8][8];
#pragma unroll
    for (int i = 0; i < 8; i++)
#pragma unroll
        for (int j = 0; j < 8; j++) acc[i][j] = 0.f;

    for (int k0 = 0; k0 < Kdim; k0 += 16) {
        // load A tile (transposed into smem, LN applied)
#pragma unroll
        for (int r = 0; r < 2; r++) {
            int row = aRow + r * 64;
            float4 v = *(const float4*)(Ab + (size_t)row * lda + k0 + aK);
            if (LN_A) {
                float mm = r ? m1 : m0, rr = r ? rs1 : rs0;
                v.x = (v.x - mm) * rr; v.y = (v.y - mm) * rr;
                v.z = (v.z - mm) * rr; v.w = (v.w - mm) * rr;
            }
            As[(aK + 0) * 132 + row] = v.x;
            As[(aK + 1) * 132 + row] = v.y;
            As[(aK + 2) * 132 + row] = v.z;
            As[(aK + 3) * 132 + row] = v.w;
        }
        // load B tile
#pragma unroll
        for (int r = 0; r < 2; r++) {
            int row = bRow + r * 8;
            *(float4*)(Bs + row * 128 + bCol) =
                *(const float4*)(Bb + (size_t)(k0 + row) * ldb + bCol);
        }
        __syncthreads();

#pragma unroll
        for (int kk = 0; kk < 16; kk++) {
            float4 a0 = *(const float4*)(As + kk * 132 + ty * 8);
            float4 a1 = *(const float4*)(As + kk * 132 + ty * 8 + 4);
            float4 b0 = *(const float4*)(Bs + kk * 128 + tx * 8);
            float4 b1 = *(const float4*)(Bs + kk * 128 + tx * 8 + 4);
            float a[8] = {a0.x,a0.y,a0.z,a0.w,a1.x,a1.y,a1.z,a1.w};
            float b[8] = {b0.x,b0.y,b0.z,b0.w,b1.x,b1.y,b1.z,b1.w};
#pragma unroll
            for (int i = 0; i < 8; i++)
#pragma unroll
                for (int j = 0; j < 8; j++) acc[i][j] = fmaf(a[i], b[j], acc[i][j]);
        }
        __syncthreads();
    }

    // epilogue
    float bia[8];
#pragma unroll
    for (int j = 0; j < 8; j++) bia[j] = bias[colBase + tx * 8 + j];

#pragma unroll
    for (int i = 0; i < 8; i++) {
        int row = rowBase + ty * 8 + i;
        float out[8];
#pragma unroll
        for (int j = 0; j < 8; j++) {
            float v = acc[i][j] + bia[j];
            out[j] = DO_GELU ? gelu_exact(v) : v;
        }
        float* cp = C + (size_t)row * ldc + colBase + tx * 8;
        *(float4*)(cp)     = make_float4(out[0], out[1], out[2], out[3]);
        *(float4*)(cp + 4) = make_float4(out[4], out[5], out[6], out[7]);
    }
}

// ---------------- K4: kNN + gather + fin build + fin LN stats ----------------
// grid: (NPTS/128, B_), block: 128 threads
__global__ __launch_bounds__(128) void align_k(
    const float* __restrict__ pc,        // [B,N,3]
    const float* __restrict__ ipc,       // [B,M,3]
    const int* __restrict__ ipmask,      // [B,M]  (bool as int32)
    const int* __restrict__ pvmask,      // [B,N]  (bool as int32)
    const float* __restrict__ ptok,      // [B,N,256]
    const float* __restrict__ imgfeat,   // [B*M,256]
    float* __restrict__ fin,             // [B*N,512]
    float* __restrict__ meanf, float* __restrict__ rstdf)
{
    __shared__ float4 sc[MIMG];     // (x,y,z, ssq-or-inf)
    __shared__ int    s_idx[128 * 3];
    __shared__ float  s_w[128 * 3];

    const int b = blockIdx.y;
    const int tid = threadIdx.x;
    const float INF = __int_as_float(0x7f800000);

    // load image patch coords + fold validity into ssq
    for (int m = tid; m < MIMG; m += 128) {
        size_t base = ((size_t)b * MIMG + m) * 3;
        float x = ipc[base + 0], y = ipc[base + 1], z = ipc[base + 2];
        bool v = ipmask[(size_t)b * MIMG + m] != 0;
        float ssq = v ? (x * x + y * y + z * z) : INF;
        sc[m] = make_float4(x, y, z, ssq);
    }
    __syncthreads();

    // phase 1: per-thread point, top-3 smallest distance
    {
        int n = blockIdx.x * 128 + tid;
        size_t pbase = ((size_t)b * NPTS + n) * 3;
        float qx = pc[pbase], qy = pc[pbase + 1], qz = pc[pbase + 2];
        float qsq = qx * qx + qy * qy + qz * qz;

        float d0 = INF, d1 = INF, d2 = INF;
        int i0 = 0, i1 = 0, i2 = 0;
        for (int m = 0; m < MIMG; m++) {
            float4 s = sc[m];
            float dot = qx * s.x + qy * s.y + qz * s.z;
            float d = qsq + s.w - 2.0f * dot;
            d = fmaxf(d, 0.0f);
            if (d < d2) {
                if (d < d1) {
                    if (d < d0) { d2=d1; i2=i1; d1=d0; i1=i0; d0=d; i0=m; }
                    else        { d2=d1; i2=i1; d1=d;  i1=m; }
                } else          { d2=d;  i2=m; }
            }
        }
        float dist0 = sqrtf(d0), dist1 = sqrtf(d1), dist2 = sqrtf(d2);
        float w0 = 1.0f / fmaxf(dist0, 1e-6f);   // inf -> 0
        float w1 = 1.0f / fmaxf(dist1, 1e-6f);
        float w2 = 1.0f / fmaxf(dist2, 1e-6f);
        float wsum = w0 + w1 + w2;
        float inv = 1.0f / fmaxf(wsum, 1e-6f);
        float pv = (pvmask[(size_t)b * NPTS + n] != 0) ? 1.0f : 0.0f;
        float scale = inv * pv;                  // fold pv into weights
        s_w[tid * 3 + 0] = w0 * scale;
        s_w[tid * 3 + 1] = w1 * scale;
        s_w[tid * 3 + 2] = w2 * scale;
        s_idx[tid * 3 + 0] = b * MIMG + i0;
        s_idx[tid * 3 + 1] = b * MIMG + i1;
        s_idx[tid * 3 + 2] = b * MIMG + i2;
    }
    __syncthreads();

    // phase 2: warp-per-point gather + fin write + LN stats
    const int wid = tid >> 5, lane = tid & 31;
    for (int q = 0; q < 32; q++) {
        int nloc = wid * 32 + q;
        int n = blockIdx.x * 128 + nloc;
        size_t row = (size_t)b * NPTS + n;
        int i0 = s_idx[nloc * 3 + 0], i1 = s_idx[nloc * 3 + 1], i2 = s_idx[nloc * 3 + 2];
        float w0 = s_w[nloc * 3 + 0], w1 = s_w[nloc * 3 + 1], w2 = s_w[nloc * 3 + 2];

        const float* f0 = imgfeat + (size_t)i0 * OD + lane * 8;
        const float* f1 = imgfeat + (size_t)i1 * OD + lane * 8;
        const float* f2 = imgfeat + (size_t)i2 * OD + lane * 8;
        float4 a0 = *(const float4*)(f0);     float4 a0b = *(const float4*)(f0 + 4);
        float4 a1 = *(const float4*)(f1);     float4 a1b = *(const float4*)(f1 + 4);
        float4 a2 = *(const float4*)(f2);     float4 a2b = *(const float4*)(f2 + 4);

        float4 al, alb;
        al.x  = w0*a0.x  + w1*a1.x  + w2*a2.x;
        al.y  = w0*a0.y  + w1*a1.y  + w2*a2.y;
        al.z  = w0*a0.z  + w1*a1.z  + w2*a2.z;
        al.w  = w0*a0.w  + w1*a1.w  + w2*a2.w;
        alb.x = w0*a0b.x + w1*a1b.x + w2*a2b.x;
        alb.y = w0*a0b.y + w1*a1b.y + w2*a2b.y;
        alb.z = w0*a0b.z + w1*a1b.z + w2*a2b.z;
        alb.w = w0*a0b.w + w1*a1b.w + w2*a2b.w;

        const float* pp = ptok + row * PD + lane * 8;
        float4 p0 = *(const float4*)(pp);
        float4 p1 = *(const float4*)(pp + 4);

        float* frow = fin + row * (2 * OD);
        *(float4*)(frow + lane * 8)           = p0;
        *(float4*)(frow + lane * 8 + 4)       = p1;
        *(float4*)(frow + OD + lane * 8)      = al;
        *(float4*)(frow + OD + lane * 8 + 4)  = alb;

        float s = p0.x+p0.y+p0.z+p0.w + p1.x+p1.y+p1.z+p1.w
                + al.x+al.y+al.z+al.w + alb.x+alb.y+alb.z+alb.w;
        float ss = p0.x*p0.x+p0.y*p0.y+p0.z*p0.z+p0.w*p0.w
                 + p1.x*p1.x+p1.y*p1.y+p1.z*p1.z+p1.w*p1.w
                 + al.x*al.x+al.y*al.y+al.z*al.z+al.w*al.w
                 + alb.x*alb.x+alb.y*alb.y+alb.z*alb.z+alb.w*alb.w;
        s = warpSum(s); ss = warpSum(ss);
        if (lane == 0) {
            float m = s / 512.0f;
            float var = ss / 512.0f - m * m;
            meanf[row] = m;
            rstdf[row] = rsqrtf(var + 1e-5f);
        }
    }
}

// ---------------- K7: out = (point + sigmoid(gate)*delta) * pv ----------------
__global__ void combine_k(const float* __restrict__ ptok, const float* __restrict__ GD,
                          const int* __restrict__ pv, float* __restrict__ out) {
    int i = blockIdx.x * blockDim.x + threadIdx.x;   // float4 index, rows*64
    int row = i >> 6;
    int c = i & 63;
    const float4 p = ((const float4*)ptok)[(size_t)row * 64 + c];
    const float4 g = ((const float4*)GD)[(size_t)row * 128 + c];
    const float4 d = ((const float4*)GD)[(size_t)row * 128 + 64 + c];
    float m = (pv[row] != 0) ? 1.0f : 0.0f;
    float4 o;
    o.x = (p.x + d.x / (1.0f + expf(-g.x))) * m;
    o.y = (p.y + d.y / (1.0f + expf(-g.y))) * m;
    o.z = (p.z + d.z / (1.0f + expf(-g.z))) * m;
    o.w = (p.w + d.w / (1.0f + expf(-g.w))) * m;
    ((float4*)out)[(size_t)row * 64 + c] = o;
}

// ---------------- launch ----------------
extern "C" void kernel_launch(void* const* d_in, const int* in_sizes, int n_in,
                              void* d_out, int out_size) {
    const float* point_token  = (const float*)d_in[0];
    const float* patch_center = (const float*)d_in[1];
    const float* image_tok    = (const float*)d_in[2];
    const float* image_coord  = (const float*)d_in[3];
    const int* pvmask = (const int*)d_in[4];
    const int* imask  = (const int*)d_in[5];
    const float* ip_ln_g = (const float*)d_in[6];
    const float* ip_ln_b = (const float*)d_in[7];
    const float* ip_w1   = (const float*)d_in[8];
    const float* ip_b1   = (const float*)d_in[9];
    const float* ip_w2   = (const float*)d_in[10];
    const float* ip_b2   = (const float*)d_in[11];
    const float* g_ln_g  = (const float*)d_in[12];
    const float* g_ln_b  = (const float*)d_in[13];
    const float* g_w1    = (const float*)d_in[14];
    const float* g_b1    = (const float*)d_in[15];
    const float* g_w2    = (const float*)d_in[16];
    const float* g_b2    = (const float*)d_in[17];
    const float* d_ln_g  = (const float*)d_in[18];
    const float* d_ln_b  = (const float*)d_in[19];
    const float* d_w1    = (const float*)d_in[20];
    const float* d_b1    = (const float*)d_in[21];
    const float* d_w2    = (const float*)d_in[22];
    const float* d_b2    = (const float*)d_in[23];
    float* out = (float*)d_out;

    float *W1ip, *b1ip, *W1g, *b1g, *W1d, *b1d;
    float *Hip, *imgfeat, *mean_img, *rstd_img;
    float *fin, *mean_fin, *rstd_fin, *Hgd, *GD;
    cudaGetSymbolAddress((void**)&W1ip, g_W1ip);
    cudaGetSymbolAddress((void**)&b1ip, g_b1ip_f);
    cudaGetSymbolAddress((void**)&W1g,  g_W1g_f);
    cudaGetSymbolAddress((void**)&b1g,  g_b1g_f);
    cudaGetSymbolAddress((void**)&W1d,  g_W1d_f);
    cudaGetSymbolAddress((void**)&b1d,  g_b1d_f);
    cudaGetSymbolAddress((void**)&Hip,  g_Hip);
    cudaGetSymbolAddress((void**)&imgfeat, g_imgfeat);
    cudaGetSymbolAddress((void**)&mean_img, g_mean_img);
    cudaGetSymbolAddress((void**)&rstd_img, g_rstd_img);
    cudaGetSymbolAddress((void**)&fin, g_fin);
    cudaGetSymbolAddress((void**)&mean_fin, g_mean_fin);
    cudaGetSymbolAddress((void**)&rstd_fin, g_rstd_fin);
    cudaGetSymbolAddress((void**)&Hgd, g_Hgd);
    cudaGetSymbolAddress((void**)&GD,  g_GD);

    // K0: fold LN affine into W1/b1
    fold_w1_k<<<(ID*HD + 255)/256, 256>>>(ip_ln_g, ip_w1, W1ip, ID, HD);
    fold_w1_k<<<(HD*HD + 255)/256, 256>>>(g_ln_g,  g_w1,  W1g,  2*OD, HD);
    fold_w1_k<<<(HD*HD + 255)/256, 256>>>(d_ln_g,  d_w1,  W1d,  2*OD, HD);
    fold_b1_k<<<2, 256>>>(ip_ln_b, ip_w1, ip_b1, b1ip, ID, HD);
    fold_b1_k<<<2, 256>>>(g_ln_b,  g_w1,  g_b1,  b1g,  2*OD, HD);
    fold_b1_k<<<2, 256>>>(d_ln_b,  d_w1,  d_b1,  b1d,  2*OD, HD);

    // K1: LN stats for image tokens
    ln_stats_k<<<ROWS_IMG, 256>>>(image_tok, ID, mean_img, rstd_img);

    // K2: Hip = gelu(LN(image_tok) @ W1ip' + b1ip')   [16384,768]x[768,512]
    sgemm_k<true, true><<<dim3(HD/128, ROWS_IMG/128), 256>>>(
        image_tok, ID, W1ip, HD, b1ip, Hip, HD, ID, mean_img, rstd_img);

    // K3: imgfeat = Hip @ ip_w2 + ip_b2               [16384,512]x[512,256]
    sgemm_k<false, false><<<dim3(OD/128, ROWS_IMG/128), 256>>>(
        Hip, HD, ip_w2, OD, ip_b2, imgfeat, OD, HD, nullptr, nullptr);

    // K4: kNN + gather + fin + fin LN stats
    align_k<<<dim3(NPTS/128, B_), 128>>>(
        patch_center, image_coord, imask, pvmask, point_token, imgfeat,
        fin, mean_fin, rstd_fin);

    // K5: Hgd = gelu(LN(fin) @ [W1g'|W1d'] + b)       [65536,512]x[512,512] x2
    sgemm_k<true, true><<<dim3(HD/128, ROWS_PT/128), 256>>>(
        fin, 2*OD, W1g, HD, b1g, Hgd, 2*HD, 2*OD, mean_fin, rstd_fin);
    sgemm_k<true, true><<<dim3(HD/128, ROWS_PT/128), 256>>>(
        fin, 2*OD, W1d, HD, b1d, Hgd + HD, 2*HD, 2*OD, mean_fin, rstd_fin);

    // K6: GD = [Hg @ g_w2 + g_b2 | Hd @ d_w2 + d_b2]  [65536,512]x[512,256] x2
    sgemm_k<false, false><<<dim3(OD/128, ROWS_PT/128), 256>>>(
        Hgd, 2*HD, g_w2, OD, g_b2, GD, 2*OD, HD, nullptr, nullptr);
    sgemm_k<false, false><<<dim3(OD/128, ROWS_PT/128), 256>>>(
        Hgd + HD, 2*HD, d_w2, OD, d_b2, GD + OD, 2*OD, HD, nullptr, nullptr);

    // K7: combine
    combine_k<<<(ROWS_PT * (OD/4)) / 256, 256>>>(point_token, GD, pvmask, out);

    (void)in_sizes; (void)n_in; (void)out_size;
}

// round 4
// speedup vs baseline: 2.1531x; 2.1531x over previous
#include <cuda_runtime.h>
#include <cstdint>

// ---------------- problem constants ----------------
#define B_     16
#define NPTS   4096
#define MIMG   1024
#define PD     256
#define ID     768
#define HD     512
#define OD     256
#define ROWS_IMG (B_*MIMG)   // 16384
#define ROWS_PT  (B_*NPTS)   // 65536

// ---------------- device scratch ----------------
__device__ float g_W1ip[ID*HD];            // [768,512]  folded ln_g, tf32
__device__ float g_Wcat[HD*(2*HD)];        // [512,1024] gate|delta folded, tf32
__device__ float g_Wip2[HD*OD];            // [512,256]  tf32
__device__ float g_Wg2[HD*OD];
__device__ float g_Wd2[HD*OD];
__device__ float g_b1ip[HD];
__device__ float g_b1cat[2*HD];
__device__ float g_part[8*1024];

__device__ float g_Xn[(size_t)ROWS_IMG*ID];         // 50 MB normalized tf32 image tokens
__device__ float g_Hip[(size_t)ROWS_IMG*HD];        // 32 MB
__device__ float g_imgfeat[(size_t)ROWS_IMG*OD];    // 16 MB
__device__ float g_fin[(size_t)ROWS_PT*(2*OD)];     // 128 MB (normalized tf32)
__device__ float g_Hgd[(size_t)ROWS_PT*(2*HD)];     // 256 MB
__device__ float g_GD[(size_t)ROWS_PT*(2*OD)];      // 128 MB

// ---------------- helpers ----------------
__device__ __forceinline__ uint32_t smem_u32(const void* p) {
    uint32_t a;
    asm("{ .reg .u64 t; cvta.to.shared.u64 t, %1; cvt.u32.u64 %0, t; }" : "=r"(a) : "l"(p));
    return a;
}
__device__ __forceinline__ float tf32r(float x) {
    uint32_t u; asm("cvt.rna.tf32.f32 %0, %1;" : "=r"(u) : "f"(x));
    return __uint_as_float(u);
}
__device__ __forceinline__ void cp16(uint32_t dst, const void* src) {
    asm volatile("cp.async.cg.shared.global [%0], [%1], 16;" :: "r"(dst), "l"(src));
}
#define CP_COMMIT() asm volatile("cp.async.commit_group;" ::: "memory")
template<int N> __device__ __forceinline__ void cp_wait() {
    asm volatile("cp.async.wait_group %0;" :: "n"(N) : "memory");
}
__device__ __forceinline__ float warpSum(float v) {
#pragma unroll
    for (int o = 16; o > 0; o >>= 1) v += __shfl_xor_sync(0xffffffffu, v, o);
    return v;
}
__device__ __forceinline__ float gelu_exact(float x) {
    return 0.5f * x * (1.0f + erff(x * 0.7071067811865476f));
}

// ---------------- prep: fold+round weights ----------------
// out[k*ldo + off + n] = tf32( (lng?lng[k]:1) * w[k*N+n] )
__global__ void fold_cvt_k(const float* __restrict__ w, const float* __restrict__ lng,
                           float* __restrict__ out, int K, int N, int ldo, int off) {
    int i = blockIdx.x * 256 + threadIdx.x;
    if (i >= K * N) return;
    int k = i / N, n = i - k * N;
    float s = lng ? lng[k] : 1.0f;
    out[(size_t)k * ldo + off + n] = tf32r(s * w[i]);
}

// ---------------- prep: bias fold (split-K) ----------------
__global__ void b1part_k(const float* __restrict__ lnb, const float* __restrict__ w1,
                         float* __restrict__ part, int K, int N) {
    int j = blockIdx.x * 128 + threadIdx.x;
    int kc = blockIdx.y;
    int kb = kc * (K / 8), ke = kb + K / 8;
    float s = 0.f;
    for (int k = kb; k < ke; k++) s += lnb[k] * w1[(size_t)k * N + j];
    part[(size_t)kc * 1024 + j] = s;
}
__global__ void b1fin_k(const float* __restrict__ b1, const float* __restrict__ part,
                        float* __restrict__ out) {
    int j = blockIdx.x * 128 + threadIdx.x;
    float s = b1[j];
#pragma unroll
    for (int c = 0; c < 8; c++) s += part[(size_t)c * 1024 + j];
    out[j] = s;
}

// ---------------- LN normalize + tf32 round (image tokens, K=768) ----------------
__global__ __launch_bounds__(256) void ln_norm_k(const float* __restrict__ X,
                                                 float* __restrict__ Y) {
    int row = blockIdx.x;
    const float* x = X + (size_t)row * ID;
    float v[3]; float s = 0.f, ss = 0.f;
#pragma unroll
    for (int j = 0; j < 3; j++) {
        v[j] = x[threadIdx.x + j * 256];
        s += v[j]; ss += v[j] * v[j];
    }
    __shared__ float sbs[8], sbss[8], fm, fr;
    int lane = threadIdx.x & 31, wid = threadIdx.x >> 5;
    s = warpSum(s); ss = warpSum(ss);
    if (lane == 0) { sbs[wid] = s; sbss[wid] = ss; }
    __syncthreads();
    if (wid == 0) {
        s  = (lane < 8) ? sbs[lane]  : 0.f;
        ss = (lane < 8) ? sbss[lane] : 0.f;
        s = warpSum(s); ss = warpSum(ss);
        if (lane == 0) {
            float m = s / (float)ID;
            fm = m;
            fr = rsqrtf(ss / (float)ID - m * m + 1e-5f);
        }
    }
    __syncthreads();
    float m = fm, r = fr;
    float* y = Y + (size_t)row * ID;
#pragma unroll
    for (int j = 0; j < 3; j++) y[threadIdx.x + j * 256] = tf32r((v[j] - m) * r);
}

// ---------------- tf32 HMMA GEMM ----------------
// C[M,N] = act( A[M,K] @ W[K,N] + bias );  A,W pre-rounded tf32 in gmem.
// 128x128 CTA tile, BK=32, 8 warps (2x4), warp tile 64x32, mma m16n8k8.
#define BM 128
#define BN 128
#define BK 32
#define A_LD 36
#define B_LD 132
#define STAGE_FLOATS (BM*A_LD + BK*B_LD)          // 8832
#define GEMM_SMEM_BYTES (2*STAGE_FLOATS*4)        // 70656

template<bool DO_GELU, bool ROUND>
__global__ __launch_bounds__(256, 2) void tc_gemm_k(
    const float* __restrict__ A, int lda,
    const float* __restrict__ W, int ldw,
    const float* __restrict__ bias,
    float* __restrict__ C, int ldc, int Kdim)
{
    extern __shared__ float sm[];
    const uint32_t smb = smem_u32(sm);
    const int tid = threadIdx.x, lane = tid & 31, wid = tid >> 5;
    const int rowBase = blockIdx.y * BM, colBase = blockIdx.x * BN;
    const int wr = wid >> 2, wc = wid & 3;

    // cp.async mapping
    const int ar = tid >> 1,  ac0 = (tid & 1) * 16;   // A: row 0..127, 16 floats
    const int bk = tid >> 3,  bn0 = (tid & 7) * 16;   // B: k 0..31, 16 floats
    const float* Abase = A + (size_t)(rowBase + ar) * lda + ac0;
    const float* Wbase = W + (size_t)bk * ldw + colBase + bn0;

    auto issue = [&](int t, int stage) {
        uint32_t as = smb + (uint32_t)(stage * STAGE_FLOATS) * 4;
        uint32_t bs = as + BM * A_LD * 4;
        const float* ap = Abase + t * BK;
        const float* wp = Wbase + (size_t)t * BK * ldw;
#pragma unroll
        for (int j = 0; j < 4; j++)
            cp16(as + (uint32_t)(ar * A_LD + ac0 + 4 * j) * 4, ap + 4 * j);
#pragma unroll
        for (int j = 0; j < 4; j++)
            cp16(bs + (uint32_t)(bk * B_LD + bn0 + 4 * j) * 4, wp + 4 * j);
    };

    float acc[4][4][4];
#pragma unroll
    for (int mi = 0; mi < 4; mi++)
#pragma unroll
        for (int ni = 0; ni < 4; ni++)
#pragma unroll
            for (int r = 0; r < 4; r++) acc[mi][ni][r] = 0.f;

    const int T = Kdim / BK;
    issue(0, 0); CP_COMMIT();
    issue(1, 1); CP_COMMIT();
    cp_wait<1>();
    __syncthreads();

    for (int t = 0; t < T; t++) {
        const float* As = sm + (t & 1) * STAGE_FLOATS;
        const float* Bs = As + BM * A_LD;
#pragma unroll
        for (int ks = 0; ks < 4; ks++) {
            const int c = ks * 8 + (lane & 3);
            uint32_t a[4][4], b[4][2];
#pragma unroll
            for (int mi = 0; mi < 4; mi++) {
                int r = wr * 64 + mi * 16 + (lane >> 2);
                a[mi][0] = __float_as_uint(As[r * A_LD + c]);
                a[mi][1] = __float_as_uint(As[(r + 8) * A_LD + c]);
                a[mi][2] = __float_as_uint(As[r * A_LD + c + 4]);
                a[mi][3] = __float_as_uint(As[(r + 8) * A_LD + c + 4]);
            }
#pragma unroll
            for (int ni = 0; ni < 4; ni++) {
                int n = wc * 32 + ni * 8 + (lane >> 2);
                b[ni][0] = __float_as_uint(Bs[c * B_LD + n]);
                b[ni][1] = __float_as_uint(Bs[(c + 4) * B_LD + n]);
            }
#pragma unroll
            for (int mi = 0; mi < 4; mi++)
#pragma unroll
                for (int ni = 0; ni < 4; ni++) {
                    asm volatile(
                        "mma.sync.aligned.m16n8k8.row.col.f32.tf32.tf32.f32 "
                        "{%0,%1,%2,%3}, {%4,%5,%6,%7}, {%8,%9}, {%0,%1,%2,%3};"
                        : "+f"(acc[mi][ni][0]), "+f"(acc[mi][ni][1]),
                          "+f"(acc[mi][ni][2]), "+f"(acc[mi][ni][3])
                        : "r"(a[mi][0]), "r"(a[mi][1]), "r"(a[mi][2]), "r"(a[mi][3]),
                          "r"(b[ni][0]), "r"(b[ni][1]));
                }
        }
        __syncthreads();
        if (t + 2 < T) {
            issue(t + 2, t & 1); CP_COMMIT();
            cp_wait<1>();
            __syncthreads();
        } else if (t + 1 < T) {
            cp_wait<0>();
            __syncthreads();
        }
    }

    // epilogue
#pragma unroll
    for (int mi = 0; mi < 4; mi++) {
        int r0 = rowBase + wr * 64 + mi * 16 + (lane >> 2);
#pragma unroll
        for (int ni = 0; ni < 4; ni++) {
            int c0 = colBase + wc * 32 + ni * 8 + 2 * (lane & 3);
            float bb0 = bias[c0], bb1 = bias[c0 + 1];
            float v0 = acc[mi][ni][0] + bb0, v1 = acc[mi][ni][1] + bb1;
            float v2 = acc[mi][ni][2] + bb0, v3 = acc[mi][ni][3] + bb1;
            if (DO_GELU) {
                v0 = gelu_exact(v0); v1 = gelu_exact(v1);
                v2 = gelu_exact(v2); v3 = gelu_exact(v3);
            }
            if (ROUND) {
                v0 = tf32r(v0); v1 = tf32r(v1); v2 = tf32r(v2); v3 = tf32r(v3);
            }
            *(float2*)(C + (size_t)r0 * ldc + c0)       = make_float2(v0, v1);
            *(float2*)(C + (size_t)(r0 + 8) * ldc + c0) = make_float2(v2, v3);
        }
    }
}

// ---------------- kNN + gather + fin build (normalized tf32) ----------------
__global__ __launch_bounds__(128) void align_k(
    const float* __restrict__ pc,        // [B,N,3]
    const float* __restrict__ ipc,       // [B,M,3]
    const int* __restrict__ ipmask,      // [B,M]
    const int* __restrict__ pvmask,      // [B,N]
    const float* __restrict__ ptok,      // [B,N,256]
    const float* __restrict__ imgfeat,   // [B*M,256]
    float* __restrict__ fin)             // [B*N,512] normalized tf32
{
    __shared__ float4 sc[MIMG];
    __shared__ int    s_idx[128 * 3];
    __shared__ float  s_w[128 * 3];

    const int b = blockIdx.y;
    const int tid = threadIdx.x;
    const float INF = __int_as_float(0x7f800000);

    for (int m = tid; m < MIMG; m += 128) {
        size_t base = ((size_t)b * MIMG + m) * 3;
        float x = ipc[base + 0], y = ipc[base + 1], z = ipc[base + 2];
        bool v = ipmask[(size_t)b * MIMG + m] != 0;
        float ssq = v ? (x * x + y * y + z * z) : INF;
        sc[m] = make_float4(x, y, z, ssq);
    }
    __syncthreads();

    {
        int n = blockIdx.x * 128 + tid;
        size_t pbase = ((size_t)b * NPTS + n) * 3;
        float qx = pc[pbase], qy = pc[pbase + 1], qz = pc[pbase + 2];
        float qsq = qx * qx + qy * qy + qz * qz;

        float d0 = INF, d1 = INF, d2 = INF;
        int i0 = 0, i1 = 0, i2 = 0;
        for (int m = 0; m < MIMG; m++) {
            float4 s = sc[m];
            float dot = qx * s.x + qy * s.y + qz * s.z;
            float d = qsq + s.w - 2.0f * dot;
            d = fmaxf(d, 0.0f);
            if (d < d2) {
                if (d < d1) {
                    if (d < d0) { d2=d1; i2=i1; d1=d0; i1=i0; d0=d; i0=m; }
                    else        { d2=d1; i2=i1; d1=d;  i1=m; }
                } else          { d2=d;  i2=m; }
            }
        }
        float w0 = 1.0f / fmaxf(sqrtf(d0), 1e-6f);
        float w1 = 1.0f / fmaxf(sqrtf(d1), 1e-6f);
        float w2 = 1.0f / fmaxf(sqrtf(d2), 1e-6f);
        float inv = 1.0f / fmaxf(w0 + w1 + w2, 1e-6f);
        float pv = (pvmask[(size_t)b * NPTS + n] != 0) ? 1.0f : 0.0f;
        float scale = inv * pv;
        s_w[tid * 3 + 0] = w0 * scale;
        s_w[tid * 3 + 1] = w1 * scale;
        s_w[tid * 3 + 2] = w2 * scale;
        s_idx[tid * 3 + 0] = b * MIMG + i0;
        s_idx[tid * 3 + 1] = b * MIMG + i1;
        s_idx[tid * 3 + 2] = b * MIMG + i2;
    }
    __syncthreads();

    const int wid = tid >> 5, lane = tid & 31;
    for (int q = 0; q < 32; q++) {
        int nloc = wid * 32 + q;
        int n = blockIdx.x * 128 + nloc;
        size_t row = (size_t)b * NPTS + n;
        int i0 = s_idx[nloc * 3 + 0], i1 = s_idx[nloc * 3 + 1], i2 = s_idx[nloc * 3 + 2];
        float w0 = s_w[nloc * 3 + 0], w1 = s_w[nloc * 3 + 1], w2 = s_w[nloc * 3 + 2];

        const float* f0 = imgfeat + (size_t)i0 * OD + lane * 8;
        const float* f1 = imgfeat + (size_t)i1 * OD + lane * 8;
        const float* f2 = imgfeat + (size_t)i2 * OD + lane * 8;
        float4 a0 = *(const float4*)(f0);     float4 a0b = *(const float4*)(f0 + 4);
        float4 a1 = *(const float4*)(f1);     float4 a1b = *(const float4*)(f1 + 4);
        float4 a2 = *(const float4*)(f2);     float4 a2b = *(const float4*)(f2 + 4);

        float v[16];
        const float* pp = ptok + row * PD + lane * 8;
        float4 p0 = *(const float4*)(pp);
        float4 p1 = *(const float4*)(pp + 4);
        v[0]=p0.x; v[1]=p0.y; v[2]=p0.z; v[3]=p0.w;
        v[4]=p1.x; v[5]=p1.y; v[6]=p1.z; v[7]=p1.w;
        v[8]  = w0*a0.x  + w1*a1.x  + w2*a2.x;
        v[9]  = w0*a0.y  + w1*a1.y  + w2*a2.y;
        v[10] = w0*a0.z  + w1*a1.z  + w2*a2.z;
        v[11] = w0*a0.w  + w1*a1.w  + w2*a2.w;
        v[12] = w0*a0b.x + w1*a1b.x + w2*a2b.x;
        v[13] = w0*a0b.y + w1*a1b.y + w2*a2b.y;
        v[14] = w0*a0b.z + w1*a1b.z + w2*a2b.z;
        v[15] = w0*a0b.w + w1*a1b.w + w2*a2b.w;

        float s = 0.f, ss = 0.f;
#pragma unroll
        for (int j = 0; j < 16; j++) { s += v[j]; ss += v[j] * v[j]; }
        s = warpSum(s); ss = warpSum(ss);
        float m = s / 512.0f;
        float rstd = rsqrtf(ss / 512.0f - m * m + 1e-5f);

        float* frow = fin + row * (2 * OD);
        float o[16];
#pragma unroll
        for (int j = 0; j < 16; j++) o[j] = tf32r((v[j] - m) * rstd);
        *(float4*)(frow + lane * 8)          = make_float4(o[0], o[1], o[2], o[3]);
        *(float4*)(frow + lane * 8 + 4)      = make_float4(o[4], o[5], o[6], o[7]);
        *(float4*)(frow + OD + lane * 8)     = make_float4(o[8], o[9], o[10], o[11]);
        *(float4*)(frow + OD + lane * 8 + 4) = make_float4(o[12], o[13], o[14], o[15]);
    }
}

// ---------------- combine ----------------
__global__ void combine_k(const float* __restrict__ ptok, const float* __restrict__ GD,
                          const int* __restrict__ pv, float* __restrict__ out) {
    int i = blockIdx.x * blockDim.x + threadIdx.x;
    int row = i >> 6;
    int c = i & 63;
    const float4 p = ((const float4*)ptok)[(size_t)row * 64 + c];
    const float4 g = ((const float4*)GD)[(size_t)row * 128 + c];
    const float4 d = ((const float4*)GD)[(size_t)row * 128 + 64 + c];
    float m = (pv[row] != 0) ? 1.0f : 0.0f;
    float4 o;
    o.x = (p.x + d.x / (1.0f + expf(-g.x))) * m;
    o.y = (p.y + d.y / (1.0f + expf(-g.y))) * m;
    o.z = (p.z + d.z / (1.0f + expf(-g.z))) * m;
    o.w = (p.w + d.w / (1.0f + expf(-g.w))) * m;
    ((float4*)out)[(size_t)row * 64 + c] = o;
}

// ---------------- launch ----------------
extern "C" void kernel_launch(void* const* d_in, const int* in_sizes, int n_in,
                              void* d_out, int out_size) {
    const float* point_token  = (const float*)d_in[0];
    const float* patch_center = (const float*)d_in[1];
    const float* image_tok    = (const float*)d_in[2];
    const float* image_coord  = (const float*)d_in[3];
    const int* pvmask = (const int*)d_in[4];
    const int* imask  = (const int*)d_in[5];
    const float* ip_ln_g = (const float*)d_in[6];
    const float* ip_ln_b = (const float*)d_in[7];
    const float* ip_w1   = (const float*)d_in[8];
    const float* ip_b1   = (const float*)d_in[9];
    const float* ip_w2   = (const float*)d_in[10];
    const float* ip_b2   = (const float*)d_in[11];
    const float* g_ln_g  = (const float*)d_in[12];
    const float* g_ln_b  = (const float*)d_in[13];
    const float* g_w1    = (const float*)d_in[14];
    const float* g_b1    = (const float*)d_in[15];
    const float* g_w2    = (const float*)d_in[16];
    const float* g_b2    = (const float*)d_in[17];
    const float* d_ln_g  = (const float*)d_in[18];
    const float* d_ln_b  = (const float*)d_in[19];
    const float* d_w1    = (const float*)d_in[20];
    const float* d_b1    = (const float*)d_in[21];
    const float* d_w2    = (const float*)d_in[22];
    const float* d_b2    = (const float*)d_in[23];
    float* out = (float*)d_out;

    float *W1ip, *Wcat, *Wip2, *Wg2, *Wd2, *b1ip, *b1cat, *part;
    float *Xn, *Hip, *imgfeat, *fin, *Hgd, *GD;
    cudaGetSymbolAddress((void**)&W1ip,  g_W1ip);
    cudaGetSymbolAddress((void**)&Wcat,  g_Wcat);
    cudaGetSymbolAddress((void**)&Wip2,  g_Wip2);
    cudaGetSymbolAddress((void**)&Wg2,   g_Wg2);
    cudaGetSymbolAddress((void**)&Wd2,   g_Wd2);
    cudaGetSymbolAddress((void**)&b1ip,  g_b1ip);
    cudaGetSymbolAddress((void**)&b1cat, g_b1cat);
    cudaGetSymbolAddress((void**)&part,  g_part);
    cudaGetSymbolAddress((void**)&Xn,      g_Xn);
    cudaGetSymbolAddress((void**)&Hip,     g_Hip);
    cudaGetSymbolAddress((void**)&imgfeat, g_imgfeat);
    cudaGetSymbolAddress((void**)&fin,     g_fin);
    cudaGetSymbolAddress((void**)&Hgd,     g_Hgd);
    cudaGetSymbolAddress((void**)&GD,      g_GD);

    cudaFuncSetAttribute(tc_gemm_k<true,  true >, cudaFuncAttributeMaxDynamicSharedMemorySize, GEMM_SMEM_BYTES);
    cudaFuncSetAttribute(tc_gemm_k<false, false>, cudaFuncAttributeMaxDynamicSharedMemorySize, GEMM_SMEM_BYTES);

    // -- weight fold + tf32 round --
    fold_cvt_k<<<(ID*HD + 255)/256, 256>>>(ip_w1, ip_ln_g, W1ip, ID, HD, HD, 0);
    fold_cvt_k<<<(HD*HD + 255)/256, 256>>>(g_w1,  g_ln_g,  Wcat, HD, HD, 2*HD, 0);
    fold_cvt_k<<<(HD*HD + 255)/256, 256>>>(d_w1,  d_ln_g,  Wcat, HD, HD, 2*HD, HD);
    fold_cvt_k<<<(HD*OD + 255)/256, 256>>>(ip_w2, nullptr, Wip2, HD, OD, OD, 0);
    fold_cvt_k<<<(HD*OD + 255)/256, 256>>>(g_w2,  nullptr, Wg2,  HD, OD, OD, 0);
    fold_cvt_k<<<(HD*OD + 255)/256, 256>>>(d_w2,  nullptr, Wd2,  HD, OD, OD, 0);

    // -- bias folds (split-K) --
    b1part_k<<<dim3(HD/128, 8), 128>>>(ip_ln_b, ip_w1, part, ID, HD);
    b1fin_k<<<HD/128, 128>>>(ip_b1, part, b1ip);
    b1part_k<<<dim3(HD/128, 8), 128>>>(g_ln_b, g_w1, part, HD, HD);
    b1fin_k<<<HD/128, 128>>>(g_b1, part, b1cat);
    b1part_k<<<dim3(HD/128, 8), 128>>>(d_ln_b, d_w1, part, HD, HD);
    b1fin_k<<<HD/128, 128>>>(d_b1, part, b1cat + HD);

    // -- normalize image tokens (tf32) --
    ln_norm_k<<<ROWS_IMG, 256>>>(image_tok, Xn);

    // G1: Hip = gelu(Xn @ W1ip + b1ip)            [16384,768]x[768,512] -> tf32
    tc_gemm_k<true, true><<<dim3(HD/128, ROWS_IMG/128), 256, GEMM_SMEM_BYTES>>>(
        Xn, ID, W1ip, HD, b1ip, Hip, HD, ID);

    // G2: imgfeat = Hip @ Wip2 + ip_b2            [16384,512]x[512,256] -> fp32
    tc_gemm_k<false, false><<<dim3(OD/128, ROWS_IMG/128), 256, GEMM_SMEM_BYTES>>>(
        Hip, HD, Wip2, OD, ip_b2, imgfeat, OD, HD);

    // kNN + gather + normalized fin (tf32)
    align_k<<<dim3(NPTS/128, B_), 128>>>(
        patch_center, image_coord, imask, pvmask, point_token, imgfeat, fin);

    // G3: Hgd = gelu(fin @ Wcat + b1cat)          [65536,512]x[512,1024] -> tf32
    tc_gemm_k<true, true><<<dim3((2*HD)/128, ROWS_PT/128), 256, GEMM_SMEM_BYTES>>>(
        fin, 2*OD, Wcat, 2*HD, b1cat, Hgd, 2*HD, 2*OD);

    // G4: GD[:, :256] = Hg @ Wg2 + g_b2           [65536,512]x[512,256]
    tc_gemm_k<false, false><<<dim3(OD/128, ROWS_PT/128), 256, GEMM_SMEM_BYTES>>>(
        Hgd, 2*HD, Wg2, OD, g_b2, GD, 2*OD, HD);

    // G5: GD[:, 256:] = Hd @ Wd2 + d_b2
    tc_gemm_k<false, false><<<dim3(OD/128, ROWS_PT/128), 256, GEMM_SMEM_BYTES>>>(
        Hgd + HD, 2*HD, Wd2, OD, d_b2, GD + OD, 2*OD, HD);

    // combine
    combine_k<<<(ROWS_PT * (OD/4)) / 256, 256>>>(point_token, GD, pvmask, out);

    (void)in_sizes; (void)n_in; (void)out_size;
}

// round 5
// speedup vs baseline: 4.3099x; 2.0017x over previous
#include <cuda_runtime.h>
#include <cuda_fp16.h>
#include <cstdint>

// ---------------- problem constants ----------------
#define B_     16
#define NPTS   4096
#define MIMG   1024
#define PD     256
#define ID     768
#define HD     512
#define OD     256
#define ROWS_IMG (B_*MIMG)   // 16384
#define ROWS_PT  (B_*NPTS)   // 65536

// ---------------- device scratch ----------------
__device__ __half g_W1ip[ID*HD];            // [768,512] folded ln_g
__device__ __half g_Wcat[HD*(2*HD)];        // [512,1024] gate|delta folded
__device__ __half g_Wip2[HD*OD];            // [512,256]
__device__ __half g_Wg2[HD*OD];
__device__ __half g_Wd2[HD*OD];
__device__ float  g_b1ip[HD];
__device__ float  g_b1cat[2*HD];
__device__ float  g_part[8*1024];

__device__ __half g_Xn[(size_t)ROWS_IMG*ID];       // 25 MB normalized image tokens
__device__ __half g_Hip[(size_t)ROWS_IMG*HD];      // 16 MB
__device__ __half g_imgfeat[(size_t)ROWS_IMG*OD];  // 8 MB
__device__ __half g_fin[(size_t)ROWS_PT*(2*OD)];   // 64 MB (normalized)
__device__ __half g_Hgd[(size_t)ROWS_PT*(2*HD)];   // 128 MB
__device__ float  g_GD[(size_t)ROWS_PT*(2*OD)];    // 128 MB

// ---------------- helpers ----------------
__device__ __forceinline__ uint32_t smem_u32(const void* p) {
    uint32_t a;
    asm("{ .reg .u64 t; cvta.to.shared.u64 t, %1; cvt.u32.u64 %0, t; }" : "=r"(a) : "l"(p));
    return a;
}
__device__ __forceinline__ void cp16(uint32_t dst, const void* src) {
    asm volatile("cp.async.cg.shared.global [%0], [%1], 16;" :: "r"(dst), "l"(src));
}
#define CP_COMMIT() asm volatile("cp.async.commit_group;" ::: "memory")
template<int N> __device__ __forceinline__ void cp_wait() {
    asm volatile("cp.async.wait_group %0;" :: "n"(N) : "memory");
}
__device__ __forceinline__ void ldsm_x4(uint32_t& r0, uint32_t& r1, uint32_t& r2, uint32_t& r3,
                                        uint32_t addr) {
    asm volatile("ldmatrix.sync.aligned.m8n8.x4.shared.b16 {%0,%1,%2,%3}, [%4];"
        : "=r"(r0), "=r"(r1), "=r"(r2), "=r"(r3) : "r"(addr));
}
__device__ __forceinline__ void ldsm_x2_t(uint32_t& r0, uint32_t& r1, uint32_t addr) {
    asm volatile("ldmatrix.sync.aligned.m8n8.x2.trans.shared.b16 {%0,%1}, [%2];"
        : "=r"(r0), "=r"(r1) : "r"(addr));
}
__device__ __forceinline__ float warpSum(float v) {
#pragma unroll
    for (int o = 16; o > 0; o >>= 1) v += __shfl_xor_sync(0xffffffffu, v, o);
    return v;
}
__device__ __forceinline__ float gelu_exact(float x) {
    return 0.5f * x * (1.0f + erff(x * 0.7071067811865476f));
}

// ---------------- prep: fold+round weights to half ----------------
__global__ void fold_cvt_k(const float* __restrict__ w, const float* __restrict__ lng,
                           __half* __restrict__ out, int K, int N, int ldo, int off) {
    int i = blockIdx.x * 256 + threadIdx.x;
    if (i >= K * N) return;
    int k = i / N, n = i - k * N;
    float s = lng ? lng[k] : 1.0f;
    out[(size_t)k * ldo + off + n] = __float2half_rn(s * w[i]);
}

// ---------------- prep: bias fold (split-K) ----------------
__global__ void b1part_k(const float* __restrict__ lnb, const float* __restrict__ w1,
                         float* __restrict__ part, int K, int N) {
    int j = blockIdx.x * 128 + threadIdx.x;
    int kc = blockIdx.y;
    int kb = kc * (K / 8), ke = kb + K / 8;
    float s = 0.f;
    for (int k = kb; k < ke; k++) s += lnb[k] * w1[(size_t)k * N + j];
    part[(size_t)kc * 1024 + j] = s;
}
__global__ void b1fin_k(const float* __restrict__ b1, const float* __restrict__ part,
                        float* __restrict__ out) {
    int j = blockIdx.x * 128 + threadIdx.x;
    float s = b1[j];
#pragma unroll
    for (int c = 0; c < 8; c++) s += part[(size_t)c * 1024 + j];
    out[j] = s;
}

// ---------------- LN normalize image tokens -> half ----------------
__global__ __launch_bounds__(256) void ln_norm_k(const float* __restrict__ X,
                                                 __half* __restrict__ Y) {
    int row = blockIdx.x;
    const float* x = X + (size_t)row * ID;
    float v[3]; float s = 0.f, ss = 0.f;
#pragma unroll
    for (int j = 0; j < 3; j++) {
        v[j] = x[threadIdx.x + j * 256];
        s += v[j]; ss += v[j] * v[j];
    }
    __shared__ float sbs[8], sbss[8], fm, fr;
    int lane = threadIdx.x & 31, wid = threadIdx.x >> 5;
    s = warpSum(s); ss = warpSum(ss);
    if (lane == 0) { sbs[wid] = s; sbss[wid] = ss; }
    __syncthreads();
    if (wid == 0) {
        s  = (lane < 8) ? sbs[lane]  : 0.f;
        ss = (lane < 8) ? sbss[lane] : 0.f;
        s = warpSum(s); ss = warpSum(ss);
        if (lane == 0) {
            float m = s / (float)ID;
            fm = m;
            fr = rsqrtf(ss / (float)ID - m * m + 1e-5f);
        }
    }
    __syncthreads();
    float m = fm, r = fr;
    __half* y = Y + (size_t)row * ID;
#pragma unroll
    for (int j = 0; j < 3; j++) y[threadIdx.x + j * 256] = __float2half_rn((v[j] - m) * r);
}

// ---------------- fp16 HMMA GEMM ----------------
// C[M,N] = act( A[M,K] @ W[K,N] + bias );  A,W half in gmem, fp32 accum.
// 128x128 CTA tile, BK=32, 8 warps (2x4), warp tile 64x32, mma m16n8k16, 3-stage cp.async.
#define BM 128
#define BN 128
#define BK 32
#define A_LDH 40
#define B_LDH 136
#define STAGE_H (BM*A_LDH + BK*B_LDH)            // 9472 halves
#define STAGE_BYTES (STAGE_H*2)                  // 18944
#define GEMM_SMEM_BYTES (3*STAGE_BYTES)          // 56832

template<bool DO_GELU, bool OUT_HALF>
__global__ __launch_bounds__(256, 2) void hgemm_k(
    const __half* __restrict__ A, int lda,
    const __half* __restrict__ W, int ldw,
    const float* __restrict__ bias,
    void* __restrict__ Cv, int ldc, int Kdim)
{
    extern __shared__ __half sm[];
    const uint32_t smb = smem_u32(sm);
    const int tid = threadIdx.x, lane = tid & 31, wid = tid >> 5;
    const int rowBase = blockIdx.y * BM, colBase = blockIdx.x * BN;
    const int wr = wid >> 2, wc = wid & 3;

    // cp.async mapping: A row=tid>>1, 16-half chunk pair; B k=tid>>3, 16-half pair
    const int ar = tid >> 1,  ach = (tid & 1) * 16;
    const int bk = tid >> 3,  bnh = (tid & 7) * 16;
    const __half* Abase = A + (size_t)(rowBase + ar) * lda + ach;
    const __half* Wbase = W + (size_t)bk * ldw + colBase + bnh;

    auto issue = [&](int t, int stage) {
        uint32_t as = smb + (uint32_t)stage * STAGE_BYTES;
        uint32_t bs = as + BM * A_LDH * 2;
        const __half* ap = Abase + t * BK;
        const __half* wp = Wbase + (size_t)t * BK * ldw;
#pragma unroll
        for (int j = 0; j < 2; j++)
            cp16(as + (uint32_t)(ar * A_LDH + ach + 8 * j) * 2, ap + 8 * j);
#pragma unroll
        for (int j = 0; j < 2; j++)
            cp16(bs + (uint32_t)(bk * B_LDH + bnh + 8 * j) * 2, wp + 8 * j);
        CP_COMMIT();
    };

    float acc[4][4][4];
#pragma unroll
    for (int mi = 0; mi < 4; mi++)
#pragma unroll
        for (int ni = 0; ni < 4; ni++)
#pragma unroll
            for (int r = 0; r < 4; r++) acc[mi][ni][r] = 0.f;

    // ldmatrix lane address components
    const int aRowL = wr * 64 + (lane & 7) + ((lane >> 3) & 1) * 8;  // + mi*16
    const int aColL = (lane >> 4) * 8;                               // + ks*16
    const int bRowL = (lane & 7) + ((lane >> 3) & 1) * 8;            // k within ks*16
    const int bColL = wc * 32;                                       // + ni*8

    const int T = Kdim / BK;
    issue(0, 0);
    issue(1, 1);

    for (int t = 0; t < T; t++) {
        if (t + 1 < T) cp_wait<1>(); else cp_wait<0>();
        __syncthreads();
        const uint32_t as = smb + (uint32_t)(t % 3) * STAGE_BYTES;
        const uint32_t bs = as + BM * A_LDH * 2;
#pragma unroll
        for (int ks = 0; ks < 2; ks++) {
            uint32_t a[4][4], b[4][2];
#pragma unroll
            for (int mi = 0; mi < 4; mi++) {
                uint32_t addr = as + (uint32_t)((aRowL + mi * 16) * A_LDH + aColL + ks * 16) * 2;
                ldsm_x4(a[mi][0], a[mi][1], a[mi][2], a[mi][3], addr);
            }
#pragma unroll
            for (int ni = 0; ni < 4; ni++) {
                uint32_t addr = bs + (uint32_t)((ks * 16 + bRowL) * B_LDH + bColL + ni * 8) * 2;
                ldsm_x2_t(b[ni][0], b[ni][1], addr);
            }
#pragma unroll
            for (int mi = 0; mi < 4; mi++)
#pragma unroll
                for (int ni = 0; ni < 4; ni++) {
                    asm volatile(
                        "mma.sync.aligned.m16n8k16.row.col.f32.f16.f16.f32 "
                        "{%0,%1,%2,%3}, {%4,%5,%6,%7}, {%8,%9}, {%0,%1,%2,%3};"
                        : "+f"(acc[mi][ni][0]), "+f"(acc[mi][ni][1]),
                          "+f"(acc[mi][ni][2]), "+f"(acc[mi][ni][3])
                        : "r"(a[mi][0]), "r"(a[mi][1]), "r"(a[mi][2]), "r"(a[mi][3]),
                          "r"(b[ni][0]), "r"(b[ni][1]));
                }
        }
        if (t + 2 < T) issue(t + 2, (t + 2) % 3);
        __syncthreads();
    }

    // epilogue
#pragma unroll
    for (int mi = 0; mi < 4; mi++) {
        int r0 = rowBase + wr * 64 + mi * 16 + (lane >> 2);
#pragma unroll
        for (int ni = 0; ni < 4; ni++) {
            int c0 = colBase + wc * 32 + ni * 8 + 2 * (lane & 3);
            float bb0 = bias[c0], bb1 = bias[c0 + 1];
            float v0 = acc[mi][ni][0] + bb0, v1 = acc[mi][ni][1] + bb1;
            float v2 = acc[mi][ni][2] + bb0, v3 = acc[mi][ni][3] + bb1;
            if (DO_GELU) {
                v0 = gelu_exact(v0); v1 = gelu_exact(v1);
                v2 = gelu_exact(v2); v3 = gelu_exact(v3);
            }
            if (OUT_HALF) {
                __half* C = (__half*)Cv;
                *(__half2*)(C + (size_t)r0 * ldc + c0)       = __floats2half2_rn(v0, v1);
                *(__half2*)(C + (size_t)(r0 + 8) * ldc + c0) = __floats2half2_rn(v2, v3);
            } else {
                float* C = (float*)Cv;
                *(float2*)(C + (size_t)r0 * ldc + c0)       = make_float2(v0, v1);
                *(float2*)(C + (size_t)(r0 + 8) * ldc + c0) = make_float2(v2, v3);
            }
        }
    }
}

// ---------------- kNN + gather + fin build (normalized half) ----------------
__global__ __launch_bounds__(128) void align_k(
    const float* __restrict__ pc,        // [B,N,3]
    const float* __restrict__ ipc,       // [B,M,3]
    const int* __restrict__ ipmask,      // [B,M]
    const int* __restrict__ pvmask,      // [B,N]
    const float* __restrict__ ptok,      // [B,N,256]
    const __half* __restrict__ imgfeat,  // [B*M,256]
    __half* __restrict__ fin)            // [B*N,512] normalized
{
    __shared__ float4 sc[MIMG];
    __shared__ int    s_idx[128 * 3];
    __shared__ float  s_w[128 * 3];

    const int b = blockIdx.y;
    const int tid = threadIdx.x;
    const float INF = __int_as_float(0x7f800000);

    for (int m = tid; m < MIMG; m += 128) {
        size_t base = ((size_t)b * MIMG + m) * 3;
        float x = ipc[base + 0], y = ipc[base + 1], z = ipc[base + 2];
        bool v = ipmask[(size_t)b * MIMG + m] != 0;
        float ssq = v ? (x * x + y * y + z * z) : INF;
        sc[m] = make_float4(x, y, z, ssq);
    }
    __syncthreads();

    {
        int n = blockIdx.x * 128 + tid;
        size_t pbase = ((size_t)b * NPTS + n) * 3;
        float qx = pc[pbase], qy = pc[pbase + 1], qz = pc[pbase + 2];
        float qsq = qx * qx + qy * qy + qz * qz;

        float d0 = INF, d1 = INF, d2 = INF;
        int i0 = 0, i1 = 0, i2 = 0;
        for (int m = 0; m < MIMG; m++) {
            float4 s = sc[m];
            float dot = qx * s.x + qy * s.y + qz * s.z;
            float d = qsq + s.w - 2.0f * dot;
            d = fmaxf(d, 0.0f);
            if (d < d2) {
                if (d < d1) {
                    if (d < d0) { d2=d1; i2=i1; d1=d0; i1=i0; d0=d; i0=m; }
                    else        { d2=d1; i2=i1; d1=d;  i1=m; }
                } else          { d2=d;  i2=m; }
            }
        }
        float w0 = 1.0f / fmaxf(sqrtf(d0), 1e-6f);
        float w1 = 1.0f / fmaxf(sqrtf(d1), 1e-6f);
        float w2 = 1.0f / fmaxf(sqrtf(d2), 1e-6f);
        float inv = 1.0f / fmaxf(w0 + w1 + w2, 1e-6f);
        float pv = (pvmask[(size_t)b * NPTS + n] != 0) ? 1.0f : 0.0f;
        float scale = inv * pv;
        s_w[tid * 3 + 0] = w0 * scale;
        s_w[tid * 3 + 1] = w1 * scale;
        s_w[tid * 3 + 2] = w2 * scale;
        s_idx[tid * 3 + 0] = b * MIMG + i0;
        s_idx[tid * 3 + 1] = b * MIMG + i1;
        s_idx[tid * 3 + 2] = b * MIMG + i2;
    }
    __syncthreads();

    const int wid = tid >> 5, lane = tid & 31;
    for (int q = 0; q < 32; q++) {
        int nloc = wid * 32 + q;
        int n = blockIdx.x * 128 + nloc;
        size_t row = (size_t)b * NPTS + n;
        int i0 = s_idx[nloc * 3 + 0], i1 = s_idx[nloc * 3 + 1], i2 = s_idx[nloc * 3 + 2];
        float w0 = s_w[nloc * 3 + 0], w1 = s_w[nloc * 3 + 1], w2 = s_w[nloc * 3 + 2];

        uint4 u0 = *(const uint4*)(imgfeat + (size_t)i0 * OD + lane * 8);
        uint4 u1 = *(const uint4*)(imgfeat + (size_t)i1 * OD + lane * 8);
        uint4 u2 = *(const uint4*)(imgfeat + (size_t)i2 * OD + lane * 8);
        const __half2* h0 = (const __half2*)&u0;
        const __half2* h1 = (const __half2*)&u1;
        const __half2* h2 = (const __half2*)&u2;

        float v[16];
        const float* pp = ptok + row * PD + lane * 8;
        float4 p0 = *(const float4*)(pp);
        float4 p1 = *(const float4*)(pp + 4);
        v[0]=p0.x; v[1]=p0.y; v[2]=p0.z; v[3]=p0.w;
        v[4]=p1.x; v[5]=p1.y; v[6]=p1.z; v[7]=p1.w;
#pragma unroll
        for (int j = 0; j < 4; j++) {
            float2 f0 = __half22float2(h0[j]);
            float2 f1 = __half22float2(h1[j]);
            float2 f2 = __half22float2(h2[j]);
            v[8 + 2*j]     = w0 * f0.x + w1 * f1.x + w2 * f2.x;
            v[8 + 2*j + 1] = w0 * f0.y + w1 * f1.y + w2 * f2.y;
        }

        float s = 0.f, ss = 0.f;
#pragma unroll
        for (int j = 0; j < 16; j++) { s += v[j]; ss += v[j] * v[j]; }
        s = warpSum(s); ss = warpSum(ss);
        float m = s / 512.0f;
        float rstd = rsqrtf(ss / 512.0f - m * m + 1e-5f);

        __half2 o2[8];
#pragma unroll
        for (int j = 0; j < 8; j++)
            o2[j] = __floats2half2_rn((v[2*j] - m) * rstd, (v[2*j+1] - m) * rstd);
        __half* frow = fin + row * (2 * OD);
        *(uint4*)(frow + lane * 8)       = *(uint4*)&o2[0];
        *(uint4*)(frow + OD + lane * 8)  = *(uint4*)&o2[4];
    }
}

// ---------------- combine ----------------
__global__ void combine_k(const float* __restrict__ ptok, const float* __restrict__ GD,
                          const int* __restrict__ pv, float* __restrict__ out) {
    int i = blockIdx.x * blockDim.x + threadIdx.x;
    int row = i >> 6;
    int c = i & 63;
    const float4 p = ((const float4*)ptok)[(size_t)row * 64 + c];
    const float4 g = ((const float4*)GD)[(size_t)row * 128 + c];
    const float4 d = ((const float4*)GD)[(size_t)row * 128 + 64 + c];
    float m = (pv[row] != 0) ? 1.0f : 0.0f;
    float4 o;
    o.x = (p.x + d.x / (1.0f + expf(-g.x))) * m;
    o.y = (p.y + d.y / (1.0f + expf(-g.y))) * m;
    o.z = (p.z + d.z / (1.0f + expf(-g.z))) * m;
    o.w = (p.w + d.w / (1.0f + expf(-g.w))) * m;
    ((float4*)out)[(size_t)row * 64 + c] = o;
}

// ---------------- launch ----------------
extern "C" void kernel_launch(void* const* d_in, const int* in_sizes, int n_in,
                              void* d_out, int out_size) {
    const float* point_token  = (const float*)d_in[0];
    const float* patch_center = (const float*)d_in[1];
    const float* image_tok    = (const float*)d_in[2];
    const float* image_coord  = (const float*)d_in[3];
    const int* pvmask = (const int*)d_in[4];
    const int* imask  = (const int*)d_in[5];
    const float* ip_ln_g = (const float*)d_in[6];
    const float* ip_ln_b = (const float*)d_in[7];
    const float* ip_w1   = (const float*)d_in[8];
    const float* ip_b1   = (const float*)d_in[9];
    const float* ip_w2   = (const float*)d_in[10];
    const float* ip_b2   = (const float*)d_in[11];
    const float* g_ln_g  = (const float*)d_in[12];
    const float* g_ln_b  = (const float*)d_in[13];
    const float* g_w1    = (const float*)d_in[14];
    const float* g_b1    = (const float*)d_in[15];
    const float* g_w2    = (const float*)d_in[16];
    const float* g_b2    = (const float*)d_in[17];
    const float* d_ln_g  = (const float*)d_in[18];
    const float* d_ln_b  = (const float*)d_in[19];
    const float* d_w1    = (const float*)d_in[20];
    const float* d_b1    = (const float*)d_in[21];
    const float* d_w2    = (const float*)d_in[22];
    const float* d_b2    = (const float*)d_in[23];
    float* out = (float*)d_out;

    __half *W1ip, *Wcat, *Wip2, *Wg2, *Wd2, *Xn, *Hip, *imgfeat, *fin, *Hgd;
    float *b1ip, *b1cat, *part, *GD;
    cudaGetSymbolAddress((void**)&W1ip,  g_W1ip);
    cudaGetSymbolAddress((void**)&Wcat,  g_Wcat);
    cudaGetSymbolAddress((void**)&Wip2,  g_Wip2);
    cudaGetSymbolAddress((void**)&Wg2,   g_Wg2);
    cudaGetSymbolAddress((void**)&Wd2,   g_Wd2);
    cudaGetSymbolAddress((void**)&b1ip,  g_b1ip);
    cudaGetSymbolAddress((void**)&b1cat, g_b1cat);
    cudaGetSymbolAddress((void**)&part,  g_part);
    cudaGetSymbolAddress((void**)&Xn,      g_Xn);
    cudaGetSymbolAddress((void**)&Hip,     g_Hip);
    cudaGetSymbolAddress((void**)&imgfeat, g_imgfeat);
    cudaGetSymbolAddress((void**)&fin,     g_fin);
    cudaGetSymbolAddress((void**)&Hgd,     g_Hgd);
    cudaGetSymbolAddress((void**)&GD,      g_GD);

    cudaFuncSetAttribute(hgemm_k<true,  true >, cudaFuncAttributeMaxDynamicSharedMemorySize, GEMM_SMEM_BYTES);
    cudaFuncSetAttribute(hgemm_k<false, true >, cudaFuncAttributeMaxDynamicSharedMemorySize, GEMM_SMEM_BYTES);
    cudaFuncSetAttribute(hgemm_k<false, false>, cudaFuncAttributeMaxDynamicSharedMemorySize, GEMM_SMEM_BYTES);

    // -- weight fold + half round --
    fold_cvt_k<<<(ID*HD + 255)/256, 256>>>(ip_w1, ip_ln_g, W1ip, ID, HD, HD, 0);
    fold_cvt_k<<<(HD*HD + 255)/256, 256>>>(g_w1,  g_ln_g,  Wcat, HD, HD, 2*HD, 0);
    fold_cvt_k<<<(HD*HD + 255)/256, 256>>>(d_w1,  d_ln_g,  Wcat, HD, HD, 2*HD, HD);
    fold_cvt_k<<<(HD*OD + 255)/256, 256>>>(ip_w2, nullptr, Wip2, HD, OD, OD, 0);
    fold_cvt_k<<<(HD*OD + 255)/256, 256>>>(g_w2,  nullptr, Wg2,  HD, OD, OD, 0);
    fold_cvt_k<<<(HD*OD + 255)/256, 256>>>(d_w2,  nullptr, Wd2,  HD, OD, OD, 0);

    // -- bias folds (split-K) --
    b1part_k<<<dim3(HD/128, 8), 128>>>(ip_ln_b, ip_w1, part, ID, HD);
    b1fin_k<<<HD/128, 128>>>(ip_b1, part, b1ip);
    b1part_k<<<dim3(HD/128, 8), 128>>>(g_ln_b, g_w1, part, HD, HD);
    b1fin_k<<<HD/128, 128>>>(g_b1, part, b1cat);
    b1part_k<<<dim3(HD/128, 8), 128>>>(d_ln_b, d_w1, part, HD, HD);
    b1fin_k<<<HD/128, 128>>>(d_b1, part, b1cat + HD);

    // -- normalize image tokens --
    ln_norm_k<<<ROWS_IMG, 256>>>(image_tok, Xn);

    // G1: Hip = gelu(Xn @ W1ip + b1ip)            [16384,768]x[768,512] -> half
    hgemm_k<true, true><<<dim3(HD/128, ROWS_IMG/128), 256, GEMM_SMEM_BYTES>>>(
        Xn, ID, W1ip, HD, b1ip, Hip, HD, ID);

    // G2: imgfeat = Hip @ Wip2 + ip_b2            [16384,512]x[512,256] -> half
    hgemm_k<false, true><<<dim3(OD/128, ROWS_IMG/128), 256, GEMM_SMEM_BYTES>>>(
        Hip, HD, Wip2, OD, ip_b2, imgfeat, OD, HD);

    // kNN + gather + normalized fin (half)
    align_k<<<dim3(NPTS/128, B_), 128>>>(
        patch_center, image_coord, imask, pvmask, point_token, imgfeat, fin);

    // G3: Hgd = gelu(fin @ Wcat + b1cat)          [65536,512]x[512,1024] -> half
    hgemm_k<true, true><<<dim3((2*HD)/128, ROWS_PT/128), 256, GEMM_SMEM_BYTES>>>(
        fin, 2*OD, Wcat, 2*HD, b1cat, Hgd, 2*HD, 2*OD);

    // G4: GD[:, :256] = Hg @ Wg2 + g_b2           [65536,512]x[512,256] -> fp32
    hgemm_k<false, false><<<dim3(OD/128, ROWS_PT/128), 256, GEMM_SMEM_BYTES>>>(
        Hgd, 2*HD, Wg2, OD, g_b2, GD, 2*OD, HD);

    // G5: GD[:, 256:] = Hd @ Wd2 + d_b2
    hgemm_k<false, false><<<dim3(OD/128, ROWS_PT/128), 256, GEMM_SMEM_BYTES>>>(
        Hgd + HD, 2*HD, Wd2, OD, d_b2, GD + OD, 2*OD, HD);

    // combine
    combine_k<<<(ROWS_PT * (OD/4)) / 256, 256>>>(point_token, GD, pvmask, out);

    (void)in_sizes; (void)n_in; (void)out_size;
}

// round 7
// speedup vs baseline: 4.4654x; 1.0361x over previous
#include <cuda_runtime.h>
#include <cuda_fp16.h>
#include <cstdint>

// ---------------- problem constants ----------------
#define B_     16
#define NPTS   4096
#define MIMG   1024
#define PD     256
#define ID     768
#define HD     512
#define OD     256
#define ROWS_IMG (B_*MIMG)   // 16384
#define ROWS_PT  (B_*NPTS)   // 65536

// ---------------- device scratch ----------------
__device__ __half g_W1ip[ID*HD];            // [768,512] folded ln_g
__device__ __half g_Wcat[HD*(2*HD)];        // [512,1024] gate|delta folded
__device__ __half g_Wip2[HD*OD];            // [512,256]
__device__ __half g_Wg2[HD*OD];
__device__ __half g_Wd2[HD*OD];
__device__ float  g_b1ip[HD];
__device__ float  g_b1cat[2*HD];
__device__ float  g_part[2*8*1024];

__device__ __half g_Xn[(size_t)ROWS_IMG*ID];       // 25 MB normalized image tokens
__device__ __half g_Hip[(size_t)ROWS_IMG*HD];      // 16 MB
__device__ __half g_imgfeat[(size_t)ROWS_IMG*OD];  // 8 MB
__device__ __half g_fin[(size_t)ROWS_PT*(2*OD)];   // 64 MB (normalized)
__device__ __half g_Hgd[(size_t)ROWS_PT*(2*HD)];   // 128 MB
__device__ __half g_gate[(size_t)ROWS_PT*OD];      // 32 MB gate logits

// ---------------- helpers ----------------
__device__ __forceinline__ uint32_t smem_u32(const void* p) {
    uint32_t a;
    asm("{ .reg .u64 t; cvta.to.shared.u64 t, %1; cvt.u32.u64 %0, t; }" : "=r"(a) : "l"(p));
    return a;
}
__device__ __forceinline__ void cp16(uint32_t dst, const void* src) {
    asm volatile("cp.async.cg.shared.global [%0], [%1], 16;" :: "r"(dst), "l"(src));
}
#define CP_COMMIT() asm volatile("cp.async.commit_group;" ::: "memory")
template<int N> __device__ __forceinline__ void cp_wait() {
    asm volatile("cp.async.wait_group %0;" :: "n"(N) : "memory");
}
__device__ __forceinline__ void ldsm_x4(uint32_t& r0, uint32_t& r1, uint32_t& r2, uint32_t& r3,
                                        uint32_t addr) {
    asm volatile("ldmatrix.sync.aligned.m8n8.x4.shared.b16 {%0,%1,%2,%3}, [%4];"
        : "=r"(r0), "=r"(r1), "=r"(r2), "=r"(r3) : "r"(addr));
}
__device__ __forceinline__ void ldsm_x2_t(uint32_t& r0, uint32_t& r1, uint32_t addr) {
    asm volatile("ldmatrix.sync.aligned.m8n8.x2.trans.shared.b16 {%0,%1}, [%2];"
        : "=r"(r0), "=r"(r1) : "r"(addr));
}
__device__ __forceinline__ float warpSum(float v) {
#pragma unroll
    for (int o = 16; o > 0; o >>= 1) v += __shfl_xor_sync(0xffffffffu, v, o);
    return v;
}
__device__ __forceinline__ float gelu_exact(float x) {
    return 0.5f * x * (1.0f + erff(x * 0.7071067811865476f));
}
__device__ __forceinline__ float sigmoidf_(float x) {
    return 1.0f / (1.0f + expf(-x));
}

// ---------------- prep: fold+round weights to half (batched) ----------------
__global__ void fold_w1gd_k(const float* __restrict__ gw, const float* __restrict__ glng,
                            const float* __restrict__ dw, const float* __restrict__ dlng,
                            __half* __restrict__ wcat) {
    int which = blockIdx.y;
    const float* w   = which ? dw : gw;
    const float* lng = which ? dlng : glng;
    int i = blockIdx.x * 256 + threadIdx.x;             // over 512*512
    int k = i >> 9, n = i & 511;
    wcat[(size_t)k * (2*HD) + which * HD + n] = __float2half_rn(lng[k] * w[i]);
}
__global__ void fold_w2x3_k(const float* __restrict__ w0, const float* __restrict__ w1,
                            const float* __restrict__ w2,
                            __half* __restrict__ o0, __half* __restrict__ o1,
                            __half* __restrict__ o2) {
    int which = blockIdx.y;
    const float* w = which == 0 ? w0 : (which == 1 ? w1 : w2);
    __half* o      = which == 0 ? o0 : (which == 1 ? o1 : o2);
    int i = blockIdx.x * 256 + threadIdx.x;             // over 512*256
    o[i] = __float2half_rn(w[i]);
}
__global__ void fold_w1ip_k(const float* __restrict__ w, const float* __restrict__ lng,
                            __half* __restrict__ out) {
    int i = blockIdx.x * 256 + threadIdx.x;             // over 768*512
    int k = i >> 9;
    out[i] = __float2half_rn(lng[k] * w[i]);
}

// ---------------- prep: bias fold (split-K) ----------------
__global__ void b1part_k(const float* __restrict__ lnb, const float* __restrict__ w1,
                         float* __restrict__ part, int K) {
    int j = blockIdx.x * 128 + threadIdx.x;
    int kc = blockIdx.y;
    int kb = kc * (K / 8), ke = kb + K / 8;
    float s = 0.f;
    for (int k = kb; k < ke; k++) s += lnb[k] * w1[(size_t)k * HD + j];
    part[(size_t)kc * 1024 + j] = s;
}
__global__ void b1part2_k(const float* __restrict__ glnb, const float* __restrict__ gw1,
                          const float* __restrict__ dlnb, const float* __restrict__ dw1,
                          float* __restrict__ part) {
    int which = blockIdx.z;
    const float* lnb = which ? dlnb : glnb;
    const float* w1  = which ? dw1  : gw1;
    int j = blockIdx.x * 128 + threadIdx.x;
    int kc = blockIdx.y;
    int kb = kc * (HD / 8), ke = kb + HD / 8;
    float s = 0.f;
    for (int k = kb; k < ke; k++) s += lnb[k] * w1[(size_t)k * HD + j];
    part[(size_t)which * 8192 + (size_t)kc * 1024 + j] = s;
}
__global__ void b1fin_k(const float* __restrict__ b1, const float* __restrict__ part,
                        float* __restrict__ out) {
    int j = blockIdx.x * 128 + threadIdx.x;
    float s = b1[j];
#pragma unroll
    for (int c = 0; c < 8; c++) s += part[(size_t)c * 1024 + j];
    out[j] = s;
}
__global__ void b1fin2_k(const float* __restrict__ gb1, const float* __restrict__ db1,
                         const float* __restrict__ part, float* __restrict__ out) {
    int which = blockIdx.y;
    const float* b1 = which ? db1 : gb1;
    int j = blockIdx.x * 128 + threadIdx.x;
    float s = b1[j];
#pragma unroll
    for (int c = 0; c < 8; c++) s += part[(size_t)which * 8192 + (size_t)c * 1024 + j];
    out[which * HD + j] = s;
}

// ---------------- LN normalize image tokens -> half ----------------
__global__ __launch_bounds__(256) void ln_norm_k(const float* __restrict__ X,
                                                 __half* __restrict__ Y) {
    int row = blockIdx.x;
    const float* x = X + (size_t)row * ID;
    float v[3]; float s = 0.f, ss = 0.f;
#pragma unroll
    for (int j = 0; j < 3; j++) {
        v[j] = x[threadIdx.x + j * 256];
        s += v[j]; ss += v[j] * v[j];
    }
    __shared__ float sbs[8], sbss[8], fm, fr;
    int lane = threadIdx.x & 31, wid = threadIdx.x >> 5;
    s = warpSum(s); ss = warpSum(ss);
    if (lane == 0) { sbs[wid] = s; sbss[wid] = ss; }
    __syncthreads();
    if (wid == 0) {
        s  = (lane < 8) ? sbs[lane]  : 0.f;
        ss = (lane < 8) ? sbss[lane] : 0.f;
        s = warpSum(s); ss = warpSum(ss);
        if (lane == 0) {
            float m = s / (float)ID;
            fm = m;
            fr = rsqrtf(ss / (float)ID - m * m + 1e-5f);
        }
    }
    __syncthreads();
    float m = fm, r = fr;
    __half* y = Y + (size_t)row * ID;
#pragma unroll
    for (int j = 0; j < 3; j++) y[threadIdx.x + j * 256] = __float2half_rn((v[j] - m) * r);
}

// ---------------- fp16 HMMA GEMM ----------------
// C[M,N] = epi( A[M,K] @ W[K,N] + bias );  A,W half in gmem, fp32 accum.
// EPI: 0 = half out, 1 = gelu->half out, 2 = combine (gate+ptok+pv -> fp32 out)
#define BM 128
#define BN 128
#define BK 32
#define A_LDH 40
#define B_LDH 136
#define STAGE_H (BM*A_LDH + BK*B_LDH)
#define STAGE_BYTES (STAGE_H*2)
#define GEMM_SMEM_BYTES (3*STAGE_BYTES)          // 56832

template<int EPI>
__global__ __launch_bounds__(256, 2) void hgemm_k(
    const __half* __restrict__ A, int lda,
    const __half* __restrict__ W, int ldw,
    const float* __restrict__ bias,
    void* __restrict__ Cv, int ldc, int Kdim,
    const __half* __restrict__ gate, const float* __restrict__ ptok,
    const int* __restrict__ pvm)
{
    extern __shared__ __half sm[];
    const uint32_t smb = smem_u32(sm);
    const int tid = threadIdx.x, lane = tid & 31, wid = tid >> 5;
    const int rowBase = blockIdx.y * BM, colBase = blockIdx.x * BN;
    const int wr = wid >> 2, wc = wid & 3;

    const int ar = tid >> 1,  ach = (tid & 1) * 16;
    const int bk = tid >> 3,  bnh = (tid & 7) * 16;
    const __half* Abase = A + (size_t)(rowBase + ar) * lda + ach;
    const __half* Wbase = W + (size_t)bk * ldw + colBase + bnh;

    auto issue = [&](int t, int stage) {
        uint32_t as = smb + (uint32_t)stage * STAGE_BYTES;
        uint32_t bs = as + BM * A_LDH * 2;
        const __half* ap = Abase + t * BK;
        const __half* wp = Wbase + (size_t)t * BK * ldw;
#pragma unroll
        for (int j = 0; j < 2; j++)
            cp16(as + (uint32_t)(ar * A_LDH + ach + 8 * j) * 2, ap + 8 * j);
#pragma unroll
        for (int j = 0; j < 2; j++)
            cp16(bs + (uint32_t)(bk * B_LDH + bnh + 8 * j) * 2, wp + 8 * j);
        CP_COMMIT();
    };

    float acc[4][4][4];
#pragma unroll
    for (int mi = 0; mi < 4; mi++)
#pragma unroll
        for (int ni = 0; ni < 4; ni++)
#pragma unroll
            for (int r = 0; r < 4; r++) acc[mi][ni][r] = 0.f;

    const int aRowL = wr * 64 + (lane & 7) + ((lane >> 3) & 1) * 8;
    const int aColL = (lane >> 4) * 8;
    const int bRowL = (lane & 7) + ((lane >> 3) & 1) * 8;
    const int bColL = wc * 32;

    const int T = Kdim / BK;
    issue(0, 0);
    issue(1, 1);

    for (int t = 0; t < T; t++) {
        if (t + 1 < T) cp_wait<1>(); else cp_wait<0>();
        __syncthreads();
        const uint32_t as = smb + (uint32_t)(t % 3) * STAGE_BYTES;
        const uint32_t bs = as + BM * A_LDH * 2;
#pragma unroll
        for (int ks = 0; ks < 2; ks++) {
            uint32_t a[4][4], b[4][2];
#pragma unroll
            for (int mi = 0; mi < 4; mi++) {
                uint32_t addr = as + (uint32_t)((aRowL + mi * 16) * A_LDH + aColL + ks * 16) * 2;
                ldsm_x4(a[mi][0], a[mi][1], a[mi][2], a[mi][3], addr);
            }
#pragma unroll
            for (int ni = 0; ni < 4; ni++) {
                uint32_t addr = bs + (uint32_t)((ks * 16 + bRowL) * B_LDH + bColL + ni * 8) * 2;
                ldsm_x2_t(b[ni][0], b[ni][1], addr);
            }
#pragma unroll
            for (int mi = 0; mi < 4; mi++)
#pragma unroll
                for (int ni = 0; ni < 4; ni++) {
                    asm volatile(
                        "mma.sync.aligned.m16n8k16.row.col.f32.f16.f16.f32 "
                        "{%0,%1,%2,%3}, {%4,%5,%6,%7}, {%8,%9}, {%0,%1,%2,%3};"
                        : "+f"(acc[mi][ni][0]), "+f"(acc[mi][ni][1]),
                          "+f"(acc[mi][ni][2]), "+f"(acc[mi][ni][3])
                        : "r"(a[mi][0]), "r"(a[mi][1]), "r"(a[mi][2]), "r"(a[mi][3]),
                          "r"(b[ni][0]), "r"(b[ni][1]));
                }
        }
        if (t + 2 < T) issue(t + 2, (t + 2) % 3);
        __syncthreads();
    }

    // epilogue
#pragma unroll
    for (int mi = 0; mi < 4; mi++) {
        int r0 = rowBase + wr * 64 + mi * 16 + (lane >> 2);
        float pv0 = 1.f, pv1 = 1.f;
        if (EPI == 2) {
            pv0 = (pvm[r0] != 0) ? 1.f : 0.f;
            pv1 = (pvm[r0 + 8] != 0) ? 1.f : 0.f;
        }
#pragma unroll
        for (int ni = 0; ni < 4; ni++) {
            int c0 = colBase + wc * 32 + ni * 8 + 2 * (lane & 3);
            float bb0 = bias[c0], bb1 = bias[c0 + 1];
            float v0 = acc[mi][ni][0] + bb0, v1 = acc[mi][ni][1] + bb1;
            float v2 = acc[mi][ni][2] + bb0, v3 = acc[mi][ni][3] + bb1;
            if (EPI == 1) {
                v0 = gelu_exact(v0); v1 = gelu_exact(v1);
                v2 = gelu_exact(v2); v3 = gelu_exact(v3);
            }
            if (EPI == 2) {
                // v = delta;  out = (p + sigmoid(g)*delta) * pv
                float2 gh0 = __half22float2(*(const __half2*)(gate + (size_t)r0 * OD + c0));
                float2 gh1 = __half22float2(*(const __half2*)(gate + (size_t)(r0 + 8) * OD + c0));
                float2 p0 = *(const float2*)(ptok + (size_t)r0 * OD + c0);
                float2 p1 = *(const float2*)(ptok + (size_t)(r0 + 8) * OD + c0);
                float* C = (float*)Cv;
                float o0 = (p0.x + sigmoidf_(gh0.x) * v0) * pv0;
                float o1 = (p0.y + sigmoidf_(gh0.y) * v1) * pv0;
                float o2 = (p1.x + sigmoidf_(gh1.x) * v2) * pv1;
                float o3 = (p1.y + sigmoidf_(gh1.y) * v3) * pv1;
                *(float2*)(C + (size_t)r0 * ldc + c0)       = make_float2(o0, o1);
                *(float2*)(C + (size_t)(r0 + 8) * ldc + c0) = make_float2(o2, o3);
            } else {
                __half* C = (__half*)Cv;
                *(__half2*)(C + (size_t)r0 * ldc + c0)       = __floats2half2_rn(v0, v1);
                *(__half2*)(C + (size_t)(r0 + 8) * ldc + c0) = __floats2half2_rn(v2, v3);
            }
        }
    }
}

// ---------------- kNN + gather + fin build (normalized half) ----------------
__global__ __launch_bounds__(128) void align_k(
    const float* __restrict__ pc,
    const float* __restrict__ ipc,
    const int* __restrict__ ipmask,
    const int* __restrict__ pvmask,
    const float* __restrict__ ptok,
    const __half* __restrict__ imgfeat,
    __half* __restrict__ fin)
{
    __shared__ float4 sc[MIMG];
    __shared__ int    s_idx[128 * 3];
    __shared__ float  s_w[128 * 3];

    const int b = blockIdx.y;
    const int tid = threadIdx.x;
    const float INF = __int_as_float(0x7f800000);

    for (int m = tid; m < MIMG; m += 128) {
        size_t base = ((size_t)b * MIMG + m) * 3;
        float x = ipc[base + 0], y = ipc[base + 1], z = ipc[base + 2];
        bool v = ipmask[(size_t)b * MIMG + m] != 0;
        float ssq = v ? (x * x + y * y + z * z) : INF;
        sc[m] = make_float4(x, y, z, ssq);
    }
    __syncthreads();

    {
        int n = blockIdx.x * 128 + tid;
        size_t pbase = ((size_t)b * NPTS + n) * 3;
        float qx = pc[pbase], qy = pc[pbase + 1], qz = pc[pbase + 2];
        float qsq = qx * qx + qy * qy + qz * qz;

        float d0 = INF, d1 = INF, d2 = INF;
        int i0 = 0, i1 = 0, i2 = 0;
        for (int m = 0; m < MIMG; m++) {
            float4 s = sc[m];
            float dot = qx * s.x + qy * s.y + qz * s.z;
            float d = qsq + s.w - 2.0f * dot;
            d = fmaxf(d, 0.0f);
            if (d < d2) {
                if (d < d1) {
                    if (d < d0) { d2=d1; i2=i1; d1=d0; i1=i0; d0=d; i0=m; }
                    else        { d2=d1; i2=i1; d1=d;  i1=m; }
                } else          { d2=d;  i2=m; }
            }
        }
        float w0 = 1.0f / fmaxf(sqrtf(d0), 1e-6f);
        float w1 = 1.0f / fmaxf(sqrtf(d1), 1e-6f);
        float w2 = 1.0f / fmaxf(sqrtf(d2), 1e-6f);
        float inv = 1.0f / fmaxf(w0 + w1 + w2, 1e-6f);
        float pv = (pvmask[(size_t)b * NPTS + n] != 0) ? 1.0f : 0.0f;
        float scale = inv * pv;
        s_w[tid * 3 + 0] = w0 * scale;
        s_w[tid * 3 + 1] = w1 * scale;
        s_w[tid * 3 + 2] = w2 * scale;
        s_idx[tid * 3 + 0] = b * MIMG + i0;
        s_idx[tid * 3 + 1] = b * MIMG + i1;
        s_idx[tid * 3 + 2] = b * MIMG + i2;
    }
    __syncthreads();

    const int wid = tid >> 5, lane = tid & 31;
    for (int q = 0; q < 32; q++) {
        int nloc = wid * 32 + q;
        int n = blockIdx.x * 128 + nloc;
        size_t row = (size_t)b * NPTS + n;
        int i0 = s_idx[nloc * 3 + 0], i1 = s_idx[nloc * 3 + 1], i2 = s_idx[nloc * 3 + 2];
        float w0 = s_w[nloc * 3 + 0], w1 = s_w[nloc * 3 + 1], w2 = s_w[nloc * 3 + 2];

        uint4 u0 = *(const uint4*)(imgfeat + (size_t)i0 * OD + lane * 8);
        uint4 u1 = *(const uint4*)(imgfeat + (size_t)i1 * OD + lane * 8);
        uint4 u2 = *(const uint4*)(imgfeat + (size_t)i2 * OD + lane * 8);
        const __half2* h0 = (const __half2*)&u0;
        const __half2* h1 = (const __half2*)&u1;
        const __half2* h2 = (const __half2*)&u2;

        float v[16];
        const float* pp = ptok + row * PD + lane * 8;
        float4 p0 = *(const float4*)(pp);
        float4 p1 = *(const float4*)(pp + 4);
        v[0]=p0.x; v[1]=p0.y; v[2]=p0.z; v[3]=p0.w;
        v[4]=p1.x; v[5]=p1.y; v[6]=p1.z; v[7]=p1.w;
#pragma unroll
        for (int j = 0; j < 4; j++) {
            float2 f0 = __half22float2(h0[j]);
            float2 f1 = __half22float2(h1[j]);
            float2 f2 = __half22float2(h2[j]);
            v[8 + 2*j]     = w0 * f0.x + w1 * f1.x + w2 * f2.x;
            v[8 + 2*j + 1] = w0 * f0.y + w1 * f1.y + w2 * f2.y;
        }

        float s = 0.f, ss = 0.f;
#pragma unroll
        for (int j = 0; j < 16; j++) { s += v[j]; ss += v[j] * v[j]; }
        s = warpSum(s); ss = warpSum(ss);
        float m = s / 512.0f;
        float rstd = rsqrtf(ss / 512.0f - m * m + 1e-5f);

        __half2 o2[8];
#pragma unroll
        for (int j = 0; j < 8; j++)
            o2[j] = __floats2half2_rn((v[2*j] - m) * rstd, (v[2*j+1] - m) * rstd);
        __half* frow = fin + row * (2 * OD);
        *(uint4*)(frow + lane * 8)       = *(uint4*)&o2[0];
        *(uint4*)(frow + OD + lane * 8)  = *(uint4*)&o2[4];
    }
}

// ---------------- launch ----------------
extern "C" void kernel_launch(void* const* d_in, const int* in_sizes, int n_in,
                              void* d_out, int out_size) {
    const float* point_token  = (const float*)d_in[0];
    const float* patch_center = (const float*)d_in[1];
    const float* image_tok    = (const float*)d_in[2];
    const float* image_coord  = (const float*)d_in[3];
    const int* pvmask = (const int*)d_in[4];
    const int* imask  = (const int*)d_in[5];
    const float* ip_ln_g = (const float*)d_in[6];
    const float* ip_ln_b = (const float*)d_in[7];
    const float* ip_w1   = (const float*)d_in[8];
    const float* ip_b1   = (const float*)d_in[9];
    const float* ip_w2   = (const float*)d_in[10];
    const float* ip_b2   = (const float*)d_in[11];
    const float* g_ln_g  = (const float*)d_in[12];
    const float* g_ln_b  = (const float*)d_in[13];
    const float* g_w1    = (const float*)d_in[14];
    const float* g_b1    = (const float*)d_in[15];
    const float* g_w2    = (const float*)d_in[16];
    const float* g_b2    = (const float*)d_in[17];
    const float* d_ln_g  = (const float*)d_in[18];
    const float* d_ln_b  = (const float*)d_in[19];
    const float* d_w1    = (const float*)d_in[20];
    const float* d_b1    = (const float*)d_in[21];
    const float* d_w2    = (const float*)d_in[22];
    const float* d_b2    = (const float*)d_in[23];
    float* out = (float*)d_out;

    __half *W1ip, *Wcat, *Wip2, *Wg2, *Wd2, *Xn, *Hip, *imgfeat, *fin, *Hgd, *gate;
    float *b1ip, *b1cat, *part;
    cudaGetSymbolAddress((void**)&W1ip,  g_W1ip);
    cudaGetSymbolAddress((void**)&Wcat,  g_Wcat);
    cudaGetSymbolAddress((void**)&Wip2,  g_Wip2);
    cudaGetSymbolAddress((void**)&Wg2,   g_Wg2);
    cudaGetSymbolAddress((void**)&Wd2,   g_Wd2);
    cudaGetSymbolAddress((void**)&b1ip,  g_b1ip);
    cudaGetSymbolAddress((void**)&b1cat, g_b1cat);
    cudaGetSymbolAddress((void**)&part,  g_part);
    cudaGetSymbolAddress((void**)&Xn,      g_Xn);
    cudaGetSymbolAddress((void**)&Hip,     g_Hip);
    cudaGetSymbolAddress((void**)&imgfeat, g_imgfeat);
    cudaGetSymbolAddress((void**)&fin,     g_fin);
    cudaGetSymbolAddress((void**)&Hgd,     g_Hgd);
    cudaGetSymbolAddress((void**)&gate,    g_gate);

    cudaFuncSetAttribute(hgemm_k<0>, cudaFuncAttributeMaxDynamicSharedMemorySize, GEMM_SMEM_BYTES);
    cudaFuncSetAttribute(hgemm_k<1>, cudaFuncAttributeMaxDynamicSharedMemorySize, GEMM_SMEM_BYTES);
    cudaFuncSetAttribute(hgemm_k<2>, cudaFuncAttributeMaxDynamicSharedMemorySize, GEMM_SMEM_BYTES);

    // -- weight fold + half round (3 launches) --
    fold_w1ip_k<<<(ID*HD)/256, 256>>>(ip_w1, ip_ln_g, W1ip);
    fold_w1gd_k<<<dim3((HD*HD)/256, 2), 256>>>(g_w1, g_ln_g, d_w1, d_ln_g, Wcat);
    fold_w2x3_k<<<dim3((HD*OD)/256, 3), 256>>>(ip_w2, g_w2, d_w2, Wip2, Wg2, Wd2);

    // -- bias folds (4 launches) --
    b1part_k<<<dim3(HD/128, 8), 128>>>(ip_ln_b, ip_w1, part, ID);
    b1fin_k<<<HD/128, 128>>>(ip_b1, part, b1ip);
    b1part2_k<<<dim3(HD/128, 8, 2), 128>>>(g_ln_b, g_w1, d_ln_b, d_w1, part);
    b1fin2_k<<<dim3(HD/128, 2), 128>>>(g_b1, d_b1, part, b1cat);

    // -- normalize image tokens --
    ln_norm_k<<<ROWS_IMG, 256>>>(image_tok, Xn);

    // G1: Hip = gelu(Xn @ W1ip + b1ip)
    hgemm_k<1><<<dim3(HD/128, ROWS_IMG/128), 256, GEMM_SMEM_BYTES>>>(
        Xn, ID, W1ip, HD, b1ip, Hip, HD, ID, nullptr, nullptr, nullptr);

    // G2: imgfeat = Hip @ Wip2 + ip_b2
    hgemm_k<0><<<dim3(OD/128, ROWS_IMG/128), 256, GEMM_SMEM_BYTES>>>(
        Hip, HD, Wip2, OD, ip_b2, imgfeat, OD, HD, nullptr, nullptr, nullptr);

    // kNN + gather + normalized fin (half)
    align_k<<<dim3(NPTS/128, B_), 128>>>(
        patch_center, image_coord, imask, pvmask, point_token, imgfeat, fin);

    // G3: Hgd = gelu(fin @ Wcat + b1cat)
    hgemm_k<1><<<dim3((2*HD)/128, ROWS_PT/128), 256, GEMM_SMEM_BYTES>>>(
        fin, 2*OD, Wcat, 2*HD, b1cat, Hgd, 2*HD, 2*OD, nullptr, nullptr, nullptr);

    // G4: gate logits (half) = Hg @ Wg2 + g_b2
    hgemm_k<0><<<dim3(OD/128, ROWS_PT/128), 256, GEMM_SMEM_BYTES>>>(
        Hgd, 2*HD, Wg2, OD, g_b2, gate, OD, HD, nullptr, nullptr, nullptr);

    // G5: out = (ptok + sigmoid(gate) * (Hd @ Wd2 + d_b2)) * pv   [fused combine]
    hgemm_k<2><<<dim3(OD/128, ROWS_PT/128), 256, GEMM_SMEM_BYTES>>>(
        Hgd + HD, 2*HD, Wd2, OD, d_b2, out, OD, HD, gate, point_token, pvmask);

    (void)in_sizes; (void)n_in; (void)out_size;
}